// round 5
// baseline (speedup 1.0000x reference)
#include <cuda_runtime.h>
#include <cuda_bf16.h>
#include <cstdint>

#define A_   50
#define T_   50
#define HID_ 128
#define H_   32
#define C_   16
#define B_   32
#define S_   2450          // T_*(A_-1)
#define HC_  512           // H_*C_
#define NEG_SLOPE 0.2f
#define NB   51            // buckets 0..50

// ---------------- scratch (device globals; no allocations allowed) --------
// g_xw layout: row-major [b][h][s][c]  (x[s,:] rows contiguous, 64B each)
__device__ __align__(16) float g_xw[(size_t)B_ * H_ * S_ * C_];
__device__ float g_asrc[B_ * H_ * S_];              // [b][h][s]
__device__ float g_adst[B_ * H_ * T_];              // [b][h][t]
__device__ float g_vdst[H_ * HID_];                 // [h][d]
__device__ __align__(16) __nv_bfloat16 g_Whi[HC_ * HID_];   // [n][k]
__device__ __align__(16) __nv_bfloat16 g_Wlo[HC_ * HID_];   // [n][k]

__device__ __forceinline__ uint32_t pack_bf16(float a, float b) {
    __nv_bfloat162 t = __floats2bfloat162_rn(a, b);
    return *reinterpret_cast<uint32_t*>(&t);
}

// mma.sync m16n8k16 row.col f32.bf16.bf16.f32
__device__ __forceinline__ void mma_bf16(float* c, const uint32_t* a, const uint32_t* b) {
    asm volatile(
        "mma.sync.aligned.m16n8k16.row.col.f32.bf16.bf16.f32 "
        "{%0,%1,%2,%3}, {%4,%5,%6,%7}, {%8,%9}, {%0,%1,%2,%3};"
        : "+f"(c[0]), "+f"(c[1]), "+f"(c[2]), "+f"(c[3])
        : "r"(a[0]), "r"(a[1]), "r"(a[2]), "r"(a[3]), "r"(b[0]), "r"(b[1]));
}

// ---- dynamic smem layout for GEMM (bytes) ----
#define ASTR   136
#define OFF_ASC   0
#define OFF_AHI   2048
#define OFF_ALO   (OFF_AHI + 34816)
#define OFF_WHI   (OFF_ALO + 34816)
#define OFF_WLO   (OFF_WHI + 34816)
#define SMEM_GEMM (OFF_WLO + 34816)
#define OFF_OUT   OFF_AHI
#define OSTR      132

// ---- dynamic smem layout for bucket-attn (bytes) ----
#define AQ1   0
#define AQ2   (AQ1 + 9808)
#define ARR   (AQ2 + 9808)            // int per s: rbkt*64 (byte offset)
#define AETH  (ARR + 9808)            // 64 sorted keys
#define APER  (AETH + 256)            // 64 perm
#define AE1   (APER + 256)
#define AE2   (AE1 + 256)
#define ABW   (AE2 + 256)             // [8][2][NB][16] f32 = 52224
#define AQW   (ABW + 52224)           // [8][2][NB] f32 = 3264
#define ABS   (AQW + 3264)            // [2][NB][16] = 6528
#define AQS   (ABS + 6528)            // [2][NB] -> 416
#define AZ    (AQS + 416)             // 64
#define SMEM_ATTN (AZ + 256)          // 93136

// ---------------- prep: bf16-split W, contract att_dst into v_dst ----------
__global__ void prep_kernel(const float* __restrict__ W,
                            const float* __restrict__ att_dst) {
    int idx = blockIdx.x * blockDim.x + threadIdx.x;
    if (idx < HID_ * HC_) {
        float w = W[idx];
        __nv_bfloat16 hi = __float2bfloat16(w);
        g_Whi[idx] = hi;
        g_Wlo[idx] = __float2bfloat16(w - __bfloat162float(hi));
    }
    if (idx < H_ * HID_) {
        int h = idx / HID_, d = idx % HID_;
        float s2 = 0.f;
        #pragma unroll
        for (int c = 0; c < C_; c++)
            s2 += W[(h * C_ + c) * HID_ + d] * att_dst[h * C_ + c];
        g_vdst[idx] = s2;
    }
}

// ---------------- mma.sync GEMM: xw = X . W^T  (bf16x3), + a_src epilogue --
__global__ __launch_bounds__(256) void gemm_mma_kernel(const float* __restrict__ hin,
                                                       const float* __restrict__ att_src) {
    extern __shared__ char smem[];
    float* asc = (float*)(smem + OFF_ASC);
    int tid = threadIdx.x, wid = tid >> 5, lane = tid & 31;
    int b = blockIdx.z;
    int s0 = blockIdx.y * 128;
    int n0 = blockIdx.x * 128;

    for (int i = tid; i < HC_; i += 256) asc[i] = att_src[i];

    #pragma unroll
    for (int i = 0; i < 16; i++) {
        int slot = tid + 256 * i;
        int row = slot >> 5, k4 = slot & 31;
        int s = s0 + row;
        float4 v = make_float4(0.f, 0.f, 0.f, 0.f);
        if (s < S_) {
            int a = s % 49 + 1, t = s / 49;
            v = *(const float4*)&hin[(((b * A_ + a) * T_ + t) * HID_) + k4 * 4];
        }
        float hx = __bfloat162float(__float2bfloat16(v.x));
        float hy = __bfloat162float(__float2bfloat16(v.y));
        float hz = __bfloat162float(__float2bfloat16(v.z));
        float hw = __bfloat162float(__float2bfloat16(v.w));
        uint2 hv = make_uint2(pack_bf16(v.x, v.y), pack_bf16(v.z, v.w));
        uint2 lv = make_uint2(pack_bf16(v.x - hx, v.y - hy), pack_bf16(v.z - hz, v.w - hw));
        size_t off = (size_t)(row * ASTR + k4 * 4) * 2;
        *(uint2*)(smem + OFF_AHI + off) = hv;
        *(uint2*)(smem + OFF_ALO + off) = lv;
    }
    #pragma unroll
    for (int i = 0; i < 8; i++) {
        int slot = tid + 256 * i;
        int row = slot >> 4, k8 = slot & 15;
        size_t off = (size_t)(row * ASTR + k8 * 8) * 2;
        *(uint4*)(smem + OFF_WHI + off) = *(const uint4*)&g_Whi[(n0 + row) * HID_ + k8 * 8];
        *(uint4*)(smem + OFF_WLO + off) = *(const uint4*)&g_Wlo[(n0 + row) * HID_ + k8 * 8];
    }
    __syncthreads();

    int wm = wid & 3, wn = wid >> 2;
    int at = lane >> 2, kq = (lane & 3) * 2;
    float acc[2][8][4];
    #pragma unroll
    for (int mt = 0; mt < 2; mt++)
        #pragma unroll
        for (int nt = 0; nt < 8; nt++)
            #pragma unroll
            for (int j = 0; j < 4; j++) acc[mt][nt][j] = 0.f;

    const uint16_t* Ah = (const uint16_t*)(smem + OFF_AHI);
    const uint16_t* Al = (const uint16_t*)(smem + OFF_ALO);
    const uint16_t* Wh = (const uint16_t*)(smem + OFF_WHI);
    const uint16_t* Wl = (const uint16_t*)(smem + OFF_WLO);

    #pragma unroll
    for (int ks = 0; ks < 8; ks++) {
        int k0 = ks * 16;
        uint32_t ah[2][4], al[2][4], bh[8][2], bl[8][2];
        #pragma unroll
        for (int mt = 0; mt < 2; mt++) {
            int r = wm * 32 + mt * 16 + at;
            int base0 = r * ASTR + k0 + kq;
            int base1 = (r + 8) * ASTR + k0 + kq;
            ah[mt][0] = *(const uint32_t*)&Ah[base0];
            ah[mt][1] = *(const uint32_t*)&Ah[base1];
            ah[mt][2] = *(const uint32_t*)&Ah[base0 + 8];
            ah[mt][3] = *(const uint32_t*)&Ah[base1 + 8];
            al[mt][0] = *(const uint32_t*)&Al[base0];
            al[mt][1] = *(const uint32_t*)&Al[base1];
            al[mt][2] = *(const uint32_t*)&Al[base0 + 8];
            al[mt][3] = *(const uint32_t*)&Al[base1 + 8];
        }
        #pragma unroll
        for (int nt = 0; nt < 8; nt++) {
            int n = wn * 64 + nt * 8 + at;
            int base = n * ASTR + k0 + kq;
            bh[nt][0] = *(const uint32_t*)&Wh[base];
            bh[nt][1] = *(const uint32_t*)&Wh[base + 8];
            bl[nt][0] = *(const uint32_t*)&Wl[base];
            bl[nt][1] = *(const uint32_t*)&Wl[base + 8];
        }
        #pragma unroll
        for (int mt = 0; mt < 2; mt++)
            #pragma unroll
            for (int nt = 0; nt < 8; nt++) {
                mma_bf16(acc[mt][nt], ah[mt], bh[nt]);
                mma_bf16(acc[mt][nt], ah[mt], bl[nt]);
                mma_bf16(acc[mt][nt], al[mt], bh[nt]);
            }
    }
    __syncthreads();

    float* outs = (float*)(smem + OFF_OUT);
    #pragma unroll
    for (int mt = 0; mt < 2; mt++) {
        int r = wm * 32 + mt * 16 + at;
        #pragma unroll
        for (int nt = 0; nt < 8; nt++) {
            int cc = wn * 64 + nt * 8 + kq;
            *(float2*)&outs[r * OSTR + cc]       = make_float2(acc[mt][nt][0], acc[mt][nt][1]);
            *(float2*)&outs[(r + 8) * OSTR + cc] = make_float2(acc[mt][nt][2], acc[mt][nt][3]);
        }
    }
    __syncthreads();

    // ---- write g_xw row-major [b,h,s,c] ----
    int h0 = n0 >> 4;
    #pragma unroll
    for (int i = 0; i < 16; i++) {
        int slot = tid + 256 * i;           // 4096 = 128 srow x 32 g
        int g = slot & 31, srow = slot >> 5;
        int s = s0 + srow;
        if (s < S_) {
            int c4 = g & 3, h_local = g >> 2;
            float4 v = *(float4*)&outs[srow * OSTR + g * 4];
            ((float4*)g_xw)[((size_t)(b * H_ + h0 + h_local) * S_ + s) * 4 + c4] = v;
        }
    }
    // ---- a_src reduction ----
    #pragma unroll
    for (int i = 0; i < 4; i++) {
        int slot = tid + 256 * i;
        int srow = slot & 127, h_local = slot >> 7;
        int s = s0 + srow;
        int hg = h0 + h_local;
        float dot = 0.f;
        #pragma unroll
        for (int cq = 0; cq < 4; cq++) {
            float4 v = *(float4*)&outs[srow * OSTR + h_local * 16 + cq * 4];
            float4 w = *(float4*)&asc[hg * C_ + cq * 4];
            dot += v.x * w.x + v.y * w.y + v.z * w.z + v.w * w.w;
        }
        if (s < S_) g_asrc[(b * H_ + hg) * S_ + s] = dot;
    }
}

// ---------------- a_dst_ego[b,h,t] = h[b,0,t,:] . v_dst[h,:] ---------------
__global__ __launch_bounds__(256) void adst_kernel(const float* __restrict__ hin) {
    __shared__ float hs[T_][HID_];
    __shared__ float vd[H_ * 129];
    int b = blockIdx.x;
    int tid = threadIdx.x;

    for (int idx = tid; idx < T_ * HID_; idx += 256) {
        int t = idx / HID_, d = idx % HID_;
        hs[t][d] = hin[((b * A_ + 0) * T_ + t) * HID_ + d];
    }
    for (int idx = tid; idx < H_ * HID_; idx += 256) {
        int h = idx / HID_, d = idx % HID_;
        vd[h * 129 + d] = g_vdst[idx];
    }
    __syncthreads();

    int h = tid & 31;
    for (int t = tid >> 5; t < T_; t += 8) {
        float acc = 0.f;
        #pragma unroll 16
        for (int d = 0; d < HID_; d++)
            acc += hs[t][d] * vd[h * 129 + d];
        g_adst[(b * H_ + h) * T_ + t] = acc;
    }
}

// ---------------- fill entire output with broadcast bias -------------------
__global__ void fill_kernel(float* __restrict__ out, const float* __restrict__ bias, int n4) {
    int idx = blockIdx.x * blockDim.x + threadIdx.x;
    int stride = gridDim.x * blockDim.x;
    for (; idx < n4; idx += stride)
        ((float4*)out)[idx] = ((const float4*)bias)[idx & 127];
}

// ---------------- bucket attention: staircase softmax, O(S*C) -------------
// one block per (b,h). Sorted thresholds -> bucket r(s) -> suffix/prefix sums.
__global__ __launch_bounds__(256) void attn_bucket_kernel(float* __restrict__ out,
                                                          const float* __restrict__ bias) {
    extern __shared__ char sm[];
    float* q1  = (float*)(sm + AQ1);
    float* q2  = (float*)(sm + AQ2);
    int*   rr  = (int*)(sm + ARR);
    float* eth = (float*)(sm + AETH);
    int*   per = (int*)(sm + APER);
    float* e1s = (float*)(sm + AE1);
    float* e2s = (float*)(sm + AE2);
    float* BW  = (float*)(sm + ABW);    // [w][arr][r][c]
    float* QW  = (float*)(sm + AQW);    // [w][arr][r]
    float* BS  = (float*)(sm + ABS);    // [arr][r][c]
    float* QS  = (float*)(sm + AQS);    // [arr][r]
    float* Zs  = (float*)(sm + AZ);

    int hh = blockIdx.x, b = blockIdx.y;
    int tid = threadIdx.x, lane = tid & 31, w = tid >> 5;

    // 1. thresholds + zero buckets
    if (tid < 64) {
        float key = __int_as_float(0x7f800000);   // +INF pad
        if (tid < T_) key = __expf(-g_adst[(b * H_ + hh) * T_ + tid]);
        eth[tid] = key;
        per[tid] = tid;
    }
    for (int i = tid; i < (52224 + 3264) / 4; i += 256)
        ((float*)(sm + ABW))[i] = 0.f;

    // 2. bitonic sort (64, ascending, with perm payload)
    for (int k = 2; k <= 64; k <<= 1) {
        for (int j = k >> 1; j > 0; j >>= 1) {
            __syncthreads();
            if (tid < 64) {
                int ixj = tid ^ j;
                if (ixj > tid) {
                    float a = eth[tid], c2 = eth[ixj];
                    bool up = ((tid & k) == 0);
                    if (up ? (a > c2) : (a < c2)) {
                        eth[tid] = c2; eth[ixj] = a;
                        int p = per[tid]; per[tid] = per[ixj]; per[ixj] = p;
                    }
                }
            }
        }
    }
    __syncthreads();

    if (tid < T_) {
        float d = g_adst[(b * H_ + hh) * T_ + per[tid]];
        e1s[tid] = __expf(d);
        e2s[tid] = __expf(NEG_SLOPE * d);
    }

    // 3. per-s: exp + bucket id (branchless lower_bound over 64)
    for (int s = tid; s < S_; s += 256) {
        float a = g_asrc[(b * H_ + hh) * S_ + s];
        float v1 = __expf(a), v2 = __expf(NEG_SLOPE * a);
        q1[s] = v1; q2[s] = v2;
        int r = 0;
        if (eth[r + 31] < v1) r += 32;
        if (eth[r + 15] < v1) r += 16;
        if (eth[r + 7]  < v1) r += 8;
        if (eth[r + 3]  < v1) r += 4;
        if (eth[r + 1]  < v1) r += 2;
        if (eth[r]      < v1) r += 1;
        rr[s] = r << 6;                  // byte offset: r * 16 floats
    }
    __syncthreads();

    // 4. phase A: per-warp bucket accumulation (conflict-free, no atomics)
    {
        const float* xrow = g_xw + (size_t)(b * H_ + hh) * S_ * C_;
        int arr = lane >> 4, c = lane & 15;
        char* bbase = sm + ABW + (size_t)((w * 2 + arr) * NB) * 64 + c * 4;
        char* qbase = sm + AQW + (size_t)((w * 2 + arr) * NB) * 4;
        const float* qarr = arr ? q2 : q1;
        bool doScalar = (c == 0);
        int s0w = w * 307, s1w = min(S_, s0w + 307);
        #pragma unroll 2
        for (int s = s0w; s < s1w; s++) {
            int ro = rr[s];
            float q = qarr[s];
            float xv = xrow[s * C_ + c];
            float* Bp = (float*)(bbase + ro);
            *Bp += q * xv;
            if (doScalar) {
                float* Qp = (float*)(qbase + (ro >> 4));
                *Qp += q;
            }
        }
    }
    __syncthreads();

    // 5. reduce 8 warp copies
    for (int i = tid; i < 2 * NB * 16; i += 256) {
        int arr2 = i / (NB * 16), rem = i % (NB * 16);
        float acc = 0.f;
        #pragma unroll
        for (int ww = 0; ww < 8; ww++)
            acc += BW[(size_t)((ww * 2 + arr2) * NB) * 16 + rem];
        BS[i] = acc;
    }
    for (int i = tid; i < 2 * NB; i += 256) {
        int arr2 = i / NB, r = i % NB;
        float acc = 0.f;
        #pragma unroll
        for (int ww = 0; ww < 8; ww++)
            acc += QW[(ww * 2 + arr2) * NB + r];
        QS[i] = acc;
    }
    __syncthreads();

    // 6. scans: arr0 suffix (r desc), arr1 prefix (r asc)
    if (tid < 32) {
        int arr2 = tid >> 4, c = tid & 15;
        float run = 0.f;
        if (arr2 == 0) {
            for (int r = NB - 1; r >= 0; r--) { run += BS[r * 16 + c]; BS[r * 16 + c] = run; }
        } else {
            for (int r = 0; r < NB; r++) { run += BS[(NB + r) * 16 + c]; BS[(NB + r) * 16 + c] = run; }
        }
    } else if (tid < 34) {
        int arr2 = tid - 32;
        float run = 0.f;
        if (arr2 == 0) {
            for (int r = NB - 1; r >= 0; r--) { run += QS[r]; QS[r] = run; }
        } else {
            for (int r = 0; r < NB; r++) { run += QS[NB + r]; QS[NB + r] = run; }
        }
    }
    __syncthreads();

    if (tid < T_)
        Zs[tid] = 1.0f / (e1s[tid] * QS[tid + 1] + e2s[tid] * QS[NB + tid]);
    __syncthreads();

    // 7. output: 50x16
    for (int i = tid; i < T_ * 16; i += 256) {
        int si = i >> 4, c = i & 15;
        int t = per[si];
        float o = Zs[si] * (e1s[si] * BS[(si + 1) * 16 + c] + e2s[si] * BS[(NB + si) * 16 + c]);
        out[((size_t)(b * A_) * T_ + t) * HC_ + hh * C_ + c] = o + bias[hh * C_ + c];
    }
}

// ---------------------------------------------------------------------------
extern "C" void kernel_launch(void* const* d_in, const int* in_sizes, int n_in,
                              void* d_out, int out_size) {
    const float* hin     = (const float*)d_in[0];
    const float* W       = (const float*)d_in[1];
    const float* att_src = (const float*)d_in[2];
    const float* att_dst = (const float*)d_in[3];
    const float* bias    = (const float*)d_in[4];
    float* out = (float*)d_out;

    cudaFuncSetAttribute(gemm_mma_kernel, cudaFuncAttributeMaxDynamicSharedMemorySize, SMEM_GEMM);
    cudaFuncSetAttribute(attn_bucket_kernel, cudaFuncAttributeMaxDynamicSharedMemorySize, SMEM_ATTN);

    prep_kernel<<<(HID_ * HC_ + 255) / 256, 256>>>(W, att_dst);

    dim3 g2(HC_ / 128, (S_ + 127) / 128, B_);
    gemm_mma_kernel<<<g2, 256, SMEM_GEMM>>>(hin, att_src);

    adst_kernel<<<B_, 256>>>(hin);

    fill_kernel<<<2048, 256>>>(out, bias, out_size / 4);

    dim3 g4(H_, B_);
    attn_bucket_kernel<<<g4, 256, SMEM_ATTN>>>(out, bias);
}

// round 6
// speedup vs baseline: 1.0989x; 1.0989x over previous
#include <cuda_runtime.h>
#include <cuda_bf16.h>
#include <cstdint>

#define A_   50
#define T_   50
#define HID_ 128
#define H_   32
#define C_   16
#define B_   32
#define S_   2450          // T_*(A_-1)
#define HC_  512           // H_*C_
#define NEG_SLOPE 0.2f
#define NB   51            // buckets 0..50

// ---------------- scratch (device globals; no allocations allowed) --------
// g_xw layout: row-major [b][h][s][c]  (x[s,:] rows contiguous, 64B each)
__device__ __align__(16) float g_xw[(size_t)B_ * H_ * S_ * C_];
__device__ float g_asrc[B_ * H_ * S_];              // [b][h][s]
__device__ float g_adst[B_ * H_ * T_];              // [b][h][t]
__device__ float g_vdst[H_ * HID_];                 // [h][d]
__device__ __align__(16) __nv_bfloat16 g_Whi[HC_ * HID_];   // [n][k]
__device__ __align__(16) __nv_bfloat16 g_Wlo[HC_ * HID_];   // [n][k]

__device__ __forceinline__ uint32_t pack_bf16(float a, float b) {
    __nv_bfloat162 t = __floats2bfloat162_rn(a, b);
    return *reinterpret_cast<uint32_t*>(&t);
}

// mma.sync m16n8k16 row.col f32.bf16.bf16.f32
__device__ __forceinline__ void mma_bf16(float* c, const uint32_t* a, const uint32_t* b) {
    asm volatile(
        "mma.sync.aligned.m16n8k16.row.col.f32.bf16.bf16.f32 "
        "{%0,%1,%2,%3}, {%4,%5,%6,%7}, {%8,%9}, {%0,%1,%2,%3};"
        : "+f"(c[0]), "+f"(c[1]), "+f"(c[2]), "+f"(c[3])
        : "r"(a[0]), "r"(a[1]), "r"(a[2]), "r"(a[3]), "r"(b[0]), "r"(b[1]));
}

// ---- dynamic smem layout for GEMM (bytes) ----
#define ASTR   136
#define OFF_ASC   0
#define OFF_AHI   2048
#define OFF_ALO   (OFF_AHI + 34816)
#define OFF_WHI   (OFF_ALO + 34816)
#define OFF_WLO   (OFF_WHI + 34816)
#define SMEM_GEMM (OFF_WLO + 34816)
#define OFF_OUT   OFF_AHI
#define OSTR      132

// ---- dynamic smem layout for bucket-attn (bytes) ----
#define AQ1   0
#define AQ2   (AQ1 + 9808)
#define ARR   (AQ2 + 9808)            // int per s: rbkt*64 (byte offset)
#define AETH  (ARR + 9808)            // 64 sorted keys
#define APER  (AETH + 256)            // 64 perm
#define AE1   (APER + 256)
#define AE2   (AE1 + 256)
#define ABW   (AE2 + 256)             // [8][2][NB][16] f32 = 52224
#define AQW   (ABW + 52224)           // [8][2][NB] f32 = 3264
#define ABS   (AQW + 3264)            // [2][NB][16] = 6528
#define AQS   (ABS + 6528)            // [2][NB] -> 416
#define AZ    (AQS + 416)             // 64
#define SMEM_ATTN (AZ + 256)          // 93136

// ---------------- prep: bf16-split W, contract att_dst into v_dst ----------
__global__ void prep_kernel(const float* __restrict__ W,
                            const float* __restrict__ att_dst) {
    int idx = blockIdx.x * blockDim.x + threadIdx.x;
    if (idx < HID_ * HC_) {
        float w = W[idx];
        __nv_bfloat16 hi = __float2bfloat16(w);
        g_Whi[idx] = hi;
        g_Wlo[idx] = __float2bfloat16(w - __bfloat162float(hi));
    }
    if (idx < H_ * HID_) {
        int h = idx / HID_, d = idx % HID_;
        float s2 = 0.f;
        #pragma unroll
        for (int c = 0; c < C_; c++)
            s2 += W[(h * C_ + c) * HID_ + d] * att_dst[h * C_ + c];
        g_vdst[idx] = s2;
    }
}

// ---------------- mma.sync GEMM: xw = X . W^T  (bf16x3), + a_src epilogue --
__global__ __launch_bounds__(256) void gemm_mma_kernel(const float* __restrict__ hin,
                                                       const float* __restrict__ att_src) {
    extern __shared__ char smem[];
    float* asc = (float*)(smem + OFF_ASC);
    int tid = threadIdx.x, wid = tid >> 5, lane = tid & 31;
    int b = blockIdx.z;
    int s0 = blockIdx.y * 128;
    int n0 = blockIdx.x * 128;

    for (int i = tid; i < HC_; i += 256) asc[i] = att_src[i];

    #pragma unroll
    for (int i = 0; i < 16; i++) {
        int slot = tid + 256 * i;
        int row = slot >> 5, k4 = slot & 31;
        int s = s0 + row;
        float4 v = make_float4(0.f, 0.f, 0.f, 0.f);
        if (s < S_) {
            int a = s % 49 + 1, t = s / 49;
            v = *(const float4*)&hin[(((b * A_ + a) * T_ + t) * HID_) + k4 * 4];
        }
        float hx = __bfloat162float(__float2bfloat16(v.x));
        float hy = __bfloat162float(__float2bfloat16(v.y));
        float hz = __bfloat162float(__float2bfloat16(v.z));
        float hw = __bfloat162float(__float2bfloat16(v.w));
        uint2 hv = make_uint2(pack_bf16(v.x, v.y), pack_bf16(v.z, v.w));
        uint2 lv = make_uint2(pack_bf16(v.x - hx, v.y - hy), pack_bf16(v.z - hz, v.w - hw));
        size_t off = (size_t)(row * ASTR + k4 * 4) * 2;
        *(uint2*)(smem + OFF_AHI + off) = hv;
        *(uint2*)(smem + OFF_ALO + off) = lv;
    }
    #pragma unroll
    for (int i = 0; i < 8; i++) {
        int slot = tid + 256 * i;
        int row = slot >> 4, k8 = slot & 15;
        size_t off = (size_t)(row * ASTR + k8 * 8) * 2;
        *(uint4*)(smem + OFF_WHI + off) = *(const uint4*)&g_Whi[(n0 + row) * HID_ + k8 * 8];
        *(uint4*)(smem + OFF_WLO + off) = *(const uint4*)&g_Wlo[(n0 + row) * HID_ + k8 * 8];
    }
    __syncthreads();

    int wm = wid & 3, wn = wid >> 2;
    int at = lane >> 2, kq = (lane & 3) * 2;
    float acc[2][8][4];
    #pragma unroll
    for (int mt = 0; mt < 2; mt++)
        #pragma unroll
        for (int nt = 0; nt < 8; nt++)
            #pragma unroll
            for (int j = 0; j < 4; j++) acc[mt][nt][j] = 0.f;

    const uint16_t* Ah = (const uint16_t*)(smem + OFF_AHI);
    const uint16_t* Al = (const uint16_t*)(smem + OFF_ALO);
    const uint16_t* Wh = (const uint16_t*)(smem + OFF_WHI);
    const uint16_t* Wl = (const uint16_t*)(smem + OFF_WLO);

    #pragma unroll
    for (int ks = 0; ks < 8; ks++) {
        int k0 = ks * 16;
        uint32_t ah[2][4], al[2][4], bh[8][2], bl[8][2];
        #pragma unroll
        for (int mt = 0; mt < 2; mt++) {
            int r = wm * 32 + mt * 16 + at;
            int base0 = r * ASTR + k0 + kq;
            int base1 = (r + 8) * ASTR + k0 + kq;
            ah[mt][0] = *(const uint32_t*)&Ah[base0];
            ah[mt][1] = *(const uint32_t*)&Ah[base1];
            ah[mt][2] = *(const uint32_t*)&Ah[base0 + 8];
            ah[mt][3] = *(const uint32_t*)&Ah[base1 + 8];
            al[mt][0] = *(const uint32_t*)&Al[base0];
            al[mt][1] = *(const uint32_t*)&Al[base1];
            al[mt][2] = *(const uint32_t*)&Al[base0 + 8];
            al[mt][3] = *(const uint32_t*)&Al[base1 + 8];
        }
        #pragma unroll
        for (int nt = 0; nt < 8; nt++) {
            int n = wn * 64 + nt * 8 + at;
            int base = n * ASTR + k0 + kq;
            bh[nt][0] = *(const uint32_t*)&Wh[base];
            bh[nt][1] = *(const uint32_t*)&Wh[base + 8];
            bl[nt][0] = *(const uint32_t*)&Wl[base];
            bl[nt][1] = *(const uint32_t*)&Wl[base + 8];
        }
        #pragma unroll
        for (int mt = 0; mt < 2; mt++)
            #pragma unroll
            for (int nt = 0; nt < 8; nt++) {
                mma_bf16(acc[mt][nt], ah[mt], bh[nt]);
                mma_bf16(acc[mt][nt], ah[mt], bl[nt]);
                mma_bf16(acc[mt][nt], al[mt], bh[nt]);
            }
    }
    __syncthreads();

    float* outs = (float*)(smem + OFF_OUT);
    #pragma unroll
    for (int mt = 0; mt < 2; mt++) {
        int r = wm * 32 + mt * 16 + at;
        #pragma unroll
        for (int nt = 0; nt < 8; nt++) {
            int cc = wn * 64 + nt * 8 + kq;
            *(float2*)&outs[r * OSTR + cc]       = make_float2(acc[mt][nt][0], acc[mt][nt][1]);
            *(float2*)&outs[(r + 8) * OSTR + cc] = make_float2(acc[mt][nt][2], acc[mt][nt][3]);
        }
    }
    __syncthreads();

    // ---- write g_xw row-major [b,h,s,c] ----
    int h0 = n0 >> 4;
    #pragma unroll
    for (int i = 0; i < 16; i++) {
        int slot = tid + 256 * i;           // 4096 = 128 srow x 32 g
        int g = slot & 31, srow = slot >> 5;
        int s = s0 + srow;
        if (s < S_) {
            int c4 = g & 3, h_local = g >> 2;
            float4 v = *(float4*)&outs[srow * OSTR + g * 4];
            ((float4*)g_xw)[((size_t)(b * H_ + h0 + h_local) * S_ + s) * 4 + c4] = v;
        }
    }
    // ---- a_src reduction ----
    #pragma unroll
    for (int i = 0; i < 4; i++) {
        int slot = tid + 256 * i;
        int srow = slot & 127, h_local = slot >> 7;
        int s = s0 + srow;
        int hg = h0 + h_local;
        float dot = 0.f;
        #pragma unroll
        for (int cq = 0; cq < 4; cq++) {
            float4 v = *(float4*)&outs[srow * OSTR + h_local * 16 + cq * 4];
            float4 w = *(float4*)&asc[hg * C_ + cq * 4];
            dot += v.x * w.x + v.y * w.y + v.z * w.z + v.w * w.w;
        }
        if (s < S_) g_asrc[(b * H_ + hg) * S_ + s] = dot;
    }
}

// ---------------- a_dst_ego[b,h,t] = h[b,0,t,:] . v_dst[h,:] ---------------
__global__ __launch_bounds__(256) void adst_kernel(const float* __restrict__ hin) {
    __shared__ float hs[T_][HID_];
    __shared__ float vd[H_ * 129];
    int b = blockIdx.x;
    int tid = threadIdx.x;

    for (int idx = tid; idx < T_ * HID_; idx += 256) {
        int t = idx / HID_, d = idx % HID_;
        hs[t][d] = hin[((b * A_ + 0) * T_ + t) * HID_ + d];
    }
    for (int idx = tid; idx < H_ * HID_; idx += 256) {
        int h = idx / HID_, d = idx % HID_;
        vd[h * 129 + d] = g_vdst[idx];
    }
    __syncthreads();

    int h = tid & 31;
    for (int t = tid >> 5; t < T_; t += 8) {
        float acc = 0.f;
        #pragma unroll 16
        for (int d = 0; d < HID_; d++)
            acc += hs[t][d] * vd[h * 129 + d];
        g_adst[(b * H_ + h) * T_ + t] = acc;
    }
}

// ---------------- fill entire output with broadcast bias -------------------
// stride % 128 == 0 -> bias float4 is loop-invariant; hoist -> pure STG stream
__global__ void fill_kernel(float* __restrict__ out, const float* __restrict__ bias, int n4) {
    int idx = blockIdx.x * blockDim.x + threadIdx.x;
    int stride = gridDim.x * blockDim.x;
    float4 v = ((const float4*)bias)[idx & 127];
    for (; idx < n4; idx += stride)
        ((float4*)out)[idx] = v;
}

// ---------------- bucket attention: staircase softmax, O(S*C) -------------
__global__ __launch_bounds__(256) void attn_bucket_kernel(float* __restrict__ out,
                                                          const float* __restrict__ bias) {
    extern __shared__ char sm[];
    float* q1  = (float*)(sm + AQ1);
    float* q2  = (float*)(sm + AQ2);
    int*   rr  = (int*)(sm + ARR);
    float* eth = (float*)(sm + AETH);
    int*   per = (int*)(sm + APER);
    float* e1s = (float*)(sm + AE1);
    float* e2s = (float*)(sm + AE2);
    float* BW  = (float*)(sm + ABW);    // [w][arr][r][c]
    float* QW  = (float*)(sm + AQW);    // [w][arr][r]
    float* BS  = (float*)(sm + ABS);    // [arr][r][c]
    float* QS  = (float*)(sm + AQS);    // [arr][r]
    float* Zs  = (float*)(sm + AZ);

    int hh = blockIdx.x, b = blockIdx.y;
    int tid = threadIdx.x, lane = tid & 31, w = tid >> 5;

    // 1. thresholds + zero buckets
    if (tid < 64) {
        float key = __int_as_float(0x7f800000);   // +INF pad
        if (tid < T_) key = __expf(-g_adst[(b * H_ + hh) * T_ + tid]);
        eth[tid] = key;
        per[tid] = tid;
    }
    for (int i = tid; i < (52224 + 3264) / 4; i += 256)
        ((float*)(sm + ABW))[i] = 0.f;

    // 2. bitonic sort (64, ascending, with perm payload)
    for (int k = 2; k <= 64; k <<= 1) {
        for (int j = k >> 1; j > 0; j >>= 1) {
            __syncthreads();
            if (tid < 64) {
                int ixj = tid ^ j;
                if (ixj > tid) {
                    float a = eth[tid], c2 = eth[ixj];
                    bool up = ((tid & k) == 0);
                    if (up ? (a > c2) : (a < c2)) {
                        eth[tid] = c2; eth[ixj] = a;
                        int p = per[tid]; per[tid] = per[ixj]; per[ixj] = p;
                    }
                }
            }
        }
    }
    __syncthreads();

    if (tid < T_) {
        float d = g_adst[(b * H_ + hh) * T_ + per[tid]];
        e1s[tid] = __expf(d);
        e2s[tid] = __expf(NEG_SLOPE * d);
    }

    // 3. per-s: exp + bucket id (branchless lower_bound over 64)
    for (int s = tid; s < S_; s += 256) {
        float a = g_asrc[(b * H_ + hh) * S_ + s];
        float v1 = __expf(a), v2 = __expf(NEG_SLOPE * a);
        q1[s] = v1; q2[s] = v2;
        int r = 0;
        if (eth[r + 31] < v1) r += 32;
        if (eth[r + 15] < v1) r += 16;
        if (eth[r + 7]  < v1) r += 8;
        if (eth[r + 3]  < v1) r += 4;
        if (eth[r + 1]  < v1) r += 2;
        if (eth[r]      < v1) r += 1;
        rr[s] = r << 6;                  // byte offset: r * 16 floats
    }
    __syncthreads();

    // 4. phase A: per-warp bucket accumulation, batched loads (MLP 8,
    //    store-free load sub-loop so LDGs/LDSes batch despite smem aliasing)
    {
        const float* xrow = g_xw + (size_t)(b * H_ + hh) * S_ * C_;
        int arr = lane >> 4, c = lane & 15;
        char* bbase = sm + ABW + (size_t)((w * 2 + arr) * NB) * 64 + c * 4;
        char* qbase = sm + AQW + (size_t)((w * 2 + arr) * NB) * 4;
        const float* qarr = arr ? q2 : q1;
        bool doScalar = (c == 0);
        int s0w = w * 307, s1w = min(S_, s0w + 307);
        int s = s0w;
        for (; s + 8 <= s1w; s += 8) {
            int ro[8]; float qv[8], xv[8];
            #pragma unroll
            for (int j = 0; j < 8; j++) {
                ro[j] = rr[s + j];
                qv[j] = qarr[s + j];
                xv[j] = xrow[(s + j) * C_ + c];
            }
            #pragma unroll
            for (int j = 0; j < 8; j++) {
                *(float*)(bbase + ro[j]) += qv[j] * xv[j];
                if (doScalar) *(float*)(qbase + (ro[j] >> 4)) += qv[j];
            }
        }
        for (; s < s1w; s++) {
            int ro = rr[s];
            float q = qarr[s];
            float xv = xrow[s * C_ + c];
            *(float*)(bbase + ro) += q * xv;
            if (doScalar) *(float*)(qbase + (ro >> 4)) += q;
        }
    }
    __syncthreads();

    // 5. reduce 8 warp copies
    for (int i = tid; i < 2 * NB * 16; i += 256) {
        int arr2 = i / (NB * 16), rem = i % (NB * 16);
        float acc = 0.f;
        #pragma unroll
        for (int ww = 0; ww < 8; ww++)
            acc += BW[(size_t)((ww * 2 + arr2) * NB) * 16 + rem];
        BS[i] = acc;
    }
    for (int i = tid; i < 2 * NB; i += 256) {
        int arr2 = i / NB, r = i % NB;
        float acc = 0.f;
        #pragma unroll
        for (int ww = 0; ww < 8; ww++)
            acc += QW[(ww * 2 + arr2) * NB + r];
        QS[i] = acc;
    }
    __syncthreads();

    // 6. scans: arr0 suffix (r desc), arr1 prefix (r asc)
    if (tid < 32) {
        int arr2 = tid >> 4, c = tid & 15;
        float run = 0.f;
        if (arr2 == 0) {
            for (int r = NB - 1; r >= 0; r--) { run += BS[r * 16 + c]; BS[r * 16 + c] = run; }
        } else {
            for (int r = 0; r < NB; r++) { run += BS[(NB + r) * 16 + c]; BS[(NB + r) * 16 + c] = run; }
        }
    } else if (tid < 34) {
        int arr2 = tid - 32;
        float run = 0.f;
        if (arr2 == 0) {
            for (int r = NB - 1; r >= 0; r--) { run += QS[r]; QS[r] = run; }
        } else {
            for (int r = 0; r < NB; r++) { run += QS[NB + r]; QS[NB + r] = run; }
        }
    }
    __syncthreads();

    if (tid < T_)
        Zs[tid] = 1.0f / (e1s[tid] * QS[tid + 1] + e2s[tid] * QS[NB + tid]);
    __syncthreads();

    // 7. output: 50x16
    for (int i = tid; i < T_ * 16; i += 256) {
        int si = i >> 4, c = i & 15;
        int t = per[si];
        float o = Zs[si] * (e1s[si] * BS[(si + 1) * 16 + c] + e2s[si] * BS[(NB + si) * 16 + c]);
        out[((size_t)(b * A_) * T_ + t) * HC_ + hh * C_ + c] = o + bias[hh * C_ + c];
    }
}

// ---------------------------------------------------------------------------
extern "C" void kernel_launch(void* const* d_in, const int* in_sizes, int n_in,
                              void* d_out, int out_size) {
    const float* hin     = (const float*)d_in[0];
    const float* W       = (const float*)d_in[1];
    const float* att_src = (const float*)d_in[2];
    const float* att_dst = (const float*)d_in[3];
    const float* bias    = (const float*)d_in[4];
    float* out = (float*)d_out;

    cudaFuncSetAttribute(gemm_mma_kernel, cudaFuncAttributeMaxDynamicSharedMemorySize, SMEM_GEMM);
    cudaFuncSetAttribute(attn_bucket_kernel, cudaFuncAttributeMaxDynamicSharedMemorySize, SMEM_ATTN);

    prep_kernel<<<(HID_ * HC_ + 255) / 256, 256>>>(W, att_dst);

    dim3 g2(HC_ / 128, (S_ + 127) / 128, B_);
    gemm_mma_kernel<<<g2, 256, SMEM_GEMM>>>(hin, att_src);

    adst_kernel<<<B_, 256>>>(hin);

    fill_kernel<<<2048, 256>>>(out, bias, out_size / 4);

    dim3 g4(H_, B_);
    attn_bucket_kernel<<<g4, 256, SMEM_ATTN>>>(out, bias);
}

// round 7
// speedup vs baseline: 1.4454x; 1.3154x over previous
#include <cuda_runtime.h>
#include <cuda_bf16.h>
#include <cstdint>

#define A_   50
#define T_   50
#define HID_ 128
#define H_   32
#define C_   16
#define B_   32
#define S_   2450          // T_*(A_-1)
#define HC_  512           // H_*C_
#define NEG_SLOPE 0.2f
#define NB   51            // buckets 0..50

// ---------------- scratch (device globals; no allocations allowed) --------
__device__ float g_vdst[H_ * HID_];                         // [h][d]
__device__ __align__(16) __nv_bfloat16 g_Whi[HC_ * HID_];   // [n][k]
__device__ __align__(16) __nv_bfloat16 g_Wlo[HC_ * HID_];   // [n][k]
__device__ float g_eth[B_ * H_ * 64];                       // sorted thresholds (+INF pad)
__device__ float g_e1[B_ * H_ * T_];
__device__ float g_e2[B_ * H_ * T_];
__device__ int   g_perm[B_ * H_ * T_];
__device__ __align__(16) float g_bkt[(size_t)B_ * H_ * 2 * NB * 16];  // 6.7 MB
__device__ float g_qbk[B_ * H_ * 2 * NB];

__device__ __forceinline__ uint32_t pack_bf16(float a, float b) {
    __nv_bfloat162 t = __floats2bfloat162_rn(a, b);
    return *reinterpret_cast<uint32_t*>(&t);
}

// mma.sync m16n8k16 row.col f32.bf16.bf16.f32
__device__ __forceinline__ void mma_bf16(float* c, const uint32_t* a, const uint32_t* b) {
    asm volatile(
        "mma.sync.aligned.m16n8k16.row.col.f32.bf16.bf16.f32 "
        "{%0,%1,%2,%3}, {%4,%5,%6,%7}, {%8,%9}, {%0,%1,%2,%3};"
        : "+f"(c[0]), "+f"(c[1]), "+f"(c[2]), "+f"(c[3])
        : "r"(a[0]), "r"(a[1]), "r"(a[2]), "r"(a[3]), "r"(b[0]), "r"(b[1]));
}

// ---- fused kernel smem layout (bytes) ----
#define ASTR   136
#define OSTR   132
#define FB_WHI  0
#define FB_WLO  34816
#define FB_AHI  69632
#define FB_ALO  104448
#define FB_OUTS FB_AHI                 // 67584 B aliases A hi+lo (consumed before staging)
#define FB_BKT  139264                 // [8 h][2 arr x 848] f32 = 54272 (arr stride 848 = 53 rows x 16)
#define FB_QBK  193536                 // [8 h][2 arr x 53] f32 = 3392
#define FB_ETH  196928                 // [8][64]
#define FB_ASC  198976                 // [8][16]
#define FB_QS1  199488                 // [8][128]
#define FB_QS2  203584
#define FB_RO   207680                 // int: r*16 (float offset)
#define SMEM_FUSED 211776
#define TRASH  816                     // 51*16: in-region scratch row for dup merge

// ---------------- prep: bf16-split W, contract att_dst into v_dst ----------
__global__ void prep_kernel(const float* __restrict__ W,
                            const float* __restrict__ att_dst) {
    int idx = blockIdx.x * blockDim.x + threadIdx.x;
    if (idx < HID_ * HC_) {
        float w = W[idx];
        __nv_bfloat16 hi = __float2bfloat16(w);
        g_Whi[idx] = hi;
        g_Wlo[idx] = __float2bfloat16(w - __bfloat162float(hi));
    }
    if (idx < H_ * HID_) {
        int h = idx / HID_, d = idx % HID_;
        float s2 = 0.f;
        #pragma unroll
        for (int c = 0; c < C_; c++)
            s2 += W[(h * C_ + c) * HID_ + d] * att_dst[h * C_ + c];
        g_vdst[idx] = s2;
    }
}

// ---------------- a_dst + sort thresholds per (b,h) ------------------------
__global__ __launch_bounds__(64) void adst_sort_kernel(const float* __restrict__ hin) {
    __shared__ float hs[T_ * 129];
    __shared__ float vd[HID_];
    __shared__ float dv[64];
    __shared__ float eth[64];
    __shared__ int per[64];
    int h = blockIdx.x, b = blockIdx.y, tid = threadIdx.x;

    for (int i = tid; i < T_ * HID_; i += 64) {
        int t = i >> 7, d = i & 127;
        hs[t * 129 + d] = hin[(size_t)(b * A_) * T_ * HID_ + i];   // ego rows contiguous
    }
    for (int i = tid; i < HID_; i += 64) vd[i] = g_vdst[h * HID_ + i];
    __syncthreads();

    float dd = 0.f, key = __int_as_float(0x7f800000);
    if (tid < T_) {
        const float* hr = &hs[tid * 129];
        float a = 0.f;
        #pragma unroll 16
        for (int d = 0; d < HID_; d++) a += hr[d] * vd[d];
        dd = a;
        key = __expf(-a);
    }
    dv[tid] = dd; eth[tid] = key; per[tid] = tid;

    for (int k = 2; k <= 64; k <<= 1) {
        for (int j = k >> 1; j > 0; j >>= 1) {
            __syncthreads();
            int ixj = tid ^ j;
            if (ixj > tid) {
                float a = eth[tid], c2 = eth[ixj];
                bool up = ((tid & k) == 0);
                if (up ? (a > c2) : (a < c2)) {
                    eth[tid] = c2; eth[ixj] = a;
                    int p = per[tid]; per[tid] = per[ixj]; per[ixj] = p;
                }
            }
        }
    }
    __syncthreads();

    g_eth[(b * H_ + h) * 64 + tid] = eth[tid];
    if (tid < T_) {
        float d2 = dv[per[tid]];
        int o = (b * H_ + h) * T_ + tid;
        g_e1[o] = __expf(d2);
        g_e2[o] = __expf(NEG_SLOPE * d2);
        g_perm[o] = per[tid];
    }
}

// ---------------- fill entire output with broadcast bias -------------------
__global__ void fill_kernel(float* __restrict__ out, const float* __restrict__ bias, int n4) {
    int idx = blockIdx.x * blockDim.x + threadIdx.x;
    int stride = gridDim.x * blockDim.x;
    float4 v = ((const float4*)bias)[idx & 127];
    for (; idx < n4; idx += stride)
        ((float4*)out)[idx] = v;
}

// ---------------- fused persistent GEMM + bucket accumulation --------------
// grid (4 head-blocks, 32 b); CTA owns 8 heads, loops all 20 s-tiles.
__global__ __launch_bounds__(256) void fused_kernel(const float* __restrict__ hin,
                                                    const float* __restrict__ att_src) {
    extern __shared__ char sm[];
    int tid = threadIdx.x, wid = tid >> 5, lane = tid & 31;
    int nb = blockIdx.x, b = blockIdx.y;
    int n0 = nb * 128, h0 = nb * 8;

    // ---- resident W (bf16 hi/lo), att_src, sorted thresholds; zero buckets
    #pragma unroll
    for (int i = 0; i < 8; i++) {
        int slot = tid + 256 * i;
        int row = slot >> 4, k8 = slot & 15;
        size_t off = (size_t)(row * ASTR + k8 * 8) * 2;
        *(uint4*)(sm + FB_WHI + off) = *(const uint4*)&g_Whi[(n0 + row) * HID_ + k8 * 8];
        *(uint4*)(sm + FB_WLO + off) = *(const uint4*)&g_Wlo[(n0 + row) * HID_ + k8 * 8];
    }
    for (int i = tid; i < 8 * 16; i += 256)
        ((float*)(sm + FB_ASC))[i] = att_src[h0 * 16 + i];
    for (int i = tid; i < 8 * 64; i += 256)
        ((float*)(sm + FB_ETH))[i] = g_eth[(b * H_ + h0) * 64 + i];
    for (int i = tid; i < (54272 + 3392) / 4; i += 256)
        ((float*)(sm + FB_BKT))[i] = 0.f;

    int wm = wid & 3, wn = wid >> 2;
    int at = lane >> 2, kq = (lane & 3) * 2;

    for (int tile = 0; tile < 20; tile++) {
        int s0 = tile * 128;
        __syncthreads();   // W/tables ready (t0); prev step2 done with outs (t>0)

        // ---- load + split-convert A tile ----
        #pragma unroll
        for (int i = 0; i < 16; i++) {
            int slot = tid + 256 * i;
            int row = slot >> 5, k4 = slot & 31;
            int s = s0 + row;
            float4 v = make_float4(0.f, 0.f, 0.f, 0.f);
            if (s < S_) {
                int a = s % 49 + 1, t = s / 49;
                v = *(const float4*)&hin[(((b * A_ + a) * T_ + t) * HID_) + k4 * 4];
            }
            float hx = __bfloat162float(__float2bfloat16(v.x));
            float hy = __bfloat162float(__float2bfloat16(v.y));
            float hz = __bfloat162float(__float2bfloat16(v.z));
            float hw = __bfloat162float(__float2bfloat16(v.w));
            uint2 hv = make_uint2(pack_bf16(v.x, v.y), pack_bf16(v.z, v.w));
            uint2 lv = make_uint2(pack_bf16(v.x - hx, v.y - hy), pack_bf16(v.z - hz, v.w - hw));
            size_t off = (size_t)(row * ASTR + k4 * 4) * 2;
            *(uint2*)(sm + FB_AHI + off) = hv;
            *(uint2*)(sm + FB_ALO + off) = lv;
        }
        __syncthreads();

        // ---- MMA mainloop ----
        float acc[2][8][4];
        #pragma unroll
        for (int mt = 0; mt < 2; mt++)
            #pragma unroll
            for (int nt = 0; nt < 8; nt++)
                #pragma unroll
                for (int j = 0; j < 4; j++) acc[mt][nt][j] = 0.f;

        const uint16_t* Ah = (const uint16_t*)(sm + FB_AHI);
        const uint16_t* Al = (const uint16_t*)(sm + FB_ALO);
        const uint16_t* Wh = (const uint16_t*)(sm + FB_WHI);
        const uint16_t* Wl = (const uint16_t*)(sm + FB_WLO);

        #pragma unroll
        for (int ks = 0; ks < 8; ks++) {
            int k0 = ks * 16;
            uint32_t ah[2][4], al[2][4], bh[8][2], bl[8][2];
            #pragma unroll
            for (int mt = 0; mt < 2; mt++) {
                int r = wm * 32 + mt * 16 + at;
                int base0 = r * ASTR + k0 + kq;
                int base1 = (r + 8) * ASTR + k0 + kq;
                ah[mt][0] = *(const uint32_t*)&Ah[base0];
                ah[mt][1] = *(const uint32_t*)&Ah[base1];
                ah[mt][2] = *(const uint32_t*)&Ah[base0 + 8];
                ah[mt][3] = *(const uint32_t*)&Ah[base1 + 8];
                al[mt][0] = *(const uint32_t*)&Al[base0];
                al[mt][1] = *(const uint32_t*)&Al[base1];
                al[mt][2] = *(const uint32_t*)&Al[base0 + 8];
                al[mt][3] = *(const uint32_t*)&Al[base1 + 8];
            }
            #pragma unroll
            for (int nt = 0; nt < 8; nt++) {
                int n = wn * 64 + nt * 8 + at;
                int base = n * ASTR + k0 + kq;
                bh[nt][0] = *(const uint32_t*)&Wh[base];
                bh[nt][1] = *(const uint32_t*)&Wh[base + 8];
                bl[nt][0] = *(const uint32_t*)&Wl[base];
                bl[nt][1] = *(const uint32_t*)&Wl[base + 8];
            }
            #pragma unroll
            for (int mt = 0; mt < 2; mt++)
                #pragma unroll
                for (int nt = 0; nt < 8; nt++) {
                    mma_bf16(acc[mt][nt], ah[mt], bh[nt]);
                    mma_bf16(acc[mt][nt], ah[mt], bl[nt]);
                    mma_bf16(acc[mt][nt], al[mt], bh[nt]);
                }
        }
        __syncthreads();    // all warps done reading A; outs may overwrite

        // ---- stage D ----
        float* outs = (float*)(sm + FB_OUTS);
        #pragma unroll
        for (int mt = 0; mt < 2; mt++) {
            int r = wm * 32 + mt * 16 + at;
            #pragma unroll
            for (int nt = 0; nt < 8; nt++) {
                int cc = wn * 64 + nt * 8 + kq;
                *(float2*)&outs[r * OSTR + cc]       = make_float2(acc[mt][nt][0], acc[mt][nt][1]);
                *(float2*)&outs[(r + 8) * OSTR + cc] = make_float2(acc[mt][nt][2], acc[mt][nt][3]);
            }
        }
        __syncthreads();

        // ---- step1: a_src -> q1,q2,bucket per (srow, head) ----
        float* qs1 = (float*)(sm + FB_QS1);
        float* qs2 = (float*)(sm + FB_QS2);
        int*   rox = (int*)(sm + FB_RO);
        #pragma unroll
        for (int i = 0; i < 4; i++) {
            int slot = tid + 256 * i;          // 1024 = 128 srow x 8 h
            int srow = slot & 127, hl = slot >> 7;
            const float* orow = outs + srow * OSTR + hl * 16;
            const float* wv = (const float*)(sm + FB_ASC) + hl * 16;
            float dot = 0.f;
            #pragma unroll
            for (int cq = 0; cq < 4; cq++) {
                float4 v = *(const float4*)&orow[cq * 4];
                float4 w = *(const float4*)&wv[cq * 4];
                dot += v.x * w.x + v.y * w.y + v.z * w.z + v.w * w.w;
            }
            float v1 = 0.f, v2 = 0.f;
            int r = 0;
            if (s0 + srow < S_) {
                v1 = __expf(dot);
                v2 = __expf(NEG_SLOPE * dot);
                const float* e = (const float*)(sm + FB_ETH) + hl * 64;
                if (e[r + 31] < v1) r += 32;
                if (e[r + 15] < v1) r += 16;
                if (e[r + 7]  < v1) r += 8;
                if (e[r + 3]  < v1) r += 4;
                if (e[r + 1]  < v1) r += 2;
                if (e[r]      < v1) r += 1;
            }
            qs1[hl * 128 + srow] = v1;
            qs2[hl * 128 + srow] = v2;
            rox[hl * 128 + srow] = r * 16;     // float offset into bucket row
        }
        __syncthreads();

        // ---- step2: warp-per-head bucket accumulation (conflict-free) ----
        {
            int hl = wid;
            int arr = lane >> 4, c = lane & 15;
            float* bk = (float*)(sm + FB_BKT) + hl * 1696 + arr * 848 + c;
            float* qb = (float*)(sm + FB_QBK) + hl * 106 + arr * 53;
            const float* qarr = (arr ? qs2 : qs1) + hl * 128;
            const int* rop = rox + hl * 128;
            const float* ox = outs + hl * 16 + c;
            bool doQ = (c == 0);
            for (int s4 = 0; s4 < 128; s4 += 4) {
                int r0 = rop[s4], r1 = rop[s4 + 1], r2 = rop[s4 + 2], r3 = rop[s4 + 3];
                float q0 = qarr[s4], q1v = qarr[s4 + 1], q2v = qarr[s4 + 2], q3v = qarr[s4 + 3];
                float x0 = ox[s4 * OSTR], x1 = ox[(s4 + 1) * OSTR];
                float x2 = ox[(s4 + 2) * OSTR], x3 = ox[(s4 + 3) * OSTR];
                float v0 = q0 * x0, v1 = q1v * x1, v2 = q2v * x2, v3 = q3v * x3;
                float w0 = q0, w1 = q1v, w2 = q2v, w3 = q3v;
                // dup-merge: guarantee r0..r3 distinct (dups -> TRASH row)
                if (r1 == r0) { v0 += v1; w0 += w1; r1 = TRASH; v1 = 0.f; w1 = 0.f; }
                if (r2 == r0) { v0 += v2; w0 += w2; r2 = TRASH; v2 = 0.f; w2 = 0.f; }
                else if (r2 == r1) { v1 += v2; w1 += w2; r2 = TRASH; v2 = 0.f; w2 = 0.f; }
                if (r3 == r0) { v0 += v3; w0 += w3; r3 = TRASH; v3 = 0.f; w3 = 0.f; }
                else if (r3 == r1) { v1 += v3; w1 += w3; r3 = TRASH; v3 = 0.f; w3 = 0.f; }
                else if (r3 == r2) { v2 += v3; w2 += w3; r3 = TRASH; v3 = 0.f; w3 = 0.f; }
                // batched loads, then stores (addresses provably distinct)
                float b0 = bk[r0], b1 = bk[r1], b2 = bk[r2], b3 = bk[r3];
                bk[r0] = b0 + v0; bk[r1] = b1 + v1; bk[r2] = b2 + v2; bk[r3] = b3 + v3;
                if (doQ) {
                    float c0 = qb[r0 >> 4], c1 = qb[r1 >> 4], c2 = qb[r2 >> 4], c3 = qb[r3 >> 4];
                    qb[r0 >> 4] = c0 + w0; qb[r1 >> 4] = c1 + w1;
                    qb[r2 >> 4] = c2 + w2; qb[r3 >> 4] = c3 + w3;
                }
            }
        }
    }
    __syncthreads();

    // ---- write bucket sums to global ----
    const float* bks = (const float*)(sm + FB_BKT);
    for (int i = tid; i < 8 * 2 * NB * 16; i += 256) {
        int c = i & 15;
        int hr = i >> 4;                    // h*102 + arr*51 + r
        int hl = hr / 102, rem = hr % 102;
        int arr = rem / NB, r = rem % NB;
        g_bkt[((size_t)((b * H_ + h0 + hl) * 2 + arr) * NB + r) * 16 + c] =
            bks[hl * 1696 + arr * 848 + r * 16 + c];
    }
    const float* qbs = (const float*)(sm + FB_QBK);
    for (int i = tid; i < 8 * 2 * NB; i += 256) {
        int hl = i / (2 * NB), rem = i % (2 * NB);
        int arr = rem / NB, r = rem % NB;
        g_qbk[((b * H_ + h0 + hl) * 2 + arr) * NB + r] = qbs[hl * 106 + arr * 53 + r];
    }
}

// ---------------- finish: scans + Z + output --------------------------------
__global__ __launch_bounds__(64) void finish_kernel(float* __restrict__ out,
                                                    const float* __restrict__ bias) {
    __shared__ float BS[2 * NB * 16];
    __shared__ float QS[2 * NB];
    __shared__ float e1s[T_], e2s[T_], Zs[T_];
    __shared__ int per[T_];
    int h = blockIdx.x, b = blockIdx.y, tid = threadIdx.x;

    const float* gb = g_bkt + (size_t)(b * H_ + h) * 2 * NB * 16;
    for (int i = tid; i < 2 * NB * 16; i += 64) BS[i] = gb[i];
    const float* gq = g_qbk + (b * H_ + h) * 2 * NB;
    for (int i = tid; i < 2 * NB; i += 64) QS[i] = gq[i];
    if (tid < T_) {
        int o = (b * H_ + h) * T_ + tid;
        e1s[tid] = g_e1[o];
        e2s[tid] = g_e2[o];
        per[tid] = g_perm[o];
    }
    __syncthreads();

    if (tid < 32) {
        int arr = tid >> 4, c = tid & 15;
        float run = 0.f;
        if (arr == 0) {
            for (int r = NB - 1; r >= 0; r--) { run += BS[r * 16 + c]; BS[r * 16 + c] = run; }
        } else {
            for (int r = 0; r < NB; r++) { run += BS[(NB + r) * 16 + c]; BS[(NB + r) * 16 + c] = run; }
        }
    } else if (tid < 34) {
        int arr = tid - 32;
        float run = 0.f;
        if (arr == 0) {
            for (int r = NB - 1; r >= 0; r--) { run += QS[r]; QS[r] = run; }
        } else {
            for (int r = 0; r < NB; r++) { run += QS[NB + r]; QS[NB + r] = run; }
        }
    }
    __syncthreads();

    if (tid < T_)
        Zs[tid] = 1.0f / (e1s[tid] * QS[tid + 1] + e2s[tid] * QS[NB + tid]);
    __syncthreads();

    for (int i = tid; i < T_ * 16; i += 64) {
        int si = i >> 4, c = i & 15;
        int t = per[si];
        float o = Zs[si] * (e1s[si] * BS[(si + 1) * 16 + c] + e2s[si] * BS[(NB + si) * 16 + c]);
        out[((size_t)(b * A_) * T_ + t) * HC_ + h * C_ + c] = o + bias[h * C_ + c];
    }
}

// ---------------------------------------------------------------------------
extern "C" void kernel_launch(void* const* d_in, const int* in_sizes, int n_in,
                              void* d_out, int out_size) {
    const float* hin     = (const float*)d_in[0];
    const float* W       = (const float*)d_in[1];
    const float* att_src = (const float*)d_in[2];
    const float* att_dst = (const float*)d_in[3];
    const float* bias    = (const float*)d_in[4];
    float* out = (float*)d_out;

    cudaFuncSetAttribute(fused_kernel, cudaFuncAttributeMaxDynamicSharedMemorySize, SMEM_FUSED);

    prep_kernel<<<(HID_ * HC_ + 255) / 256, 256>>>(W, att_dst);

    dim3 gs(H_, B_);
    adst_sort_kernel<<<gs, 64>>>(hin);

    fill_kernel<<<2048, 256>>>(out, bias, out_size / 4);

    dim3 gf(4, B_);
    fused_kernel<<<gf, 256, SMEM_FUSED>>>(hin, att_src);

    finish_kernel<<<gs, 64>>>(out, bias);
}